// round 10
// baseline (speedup 1.0000x reference)
#include <cuda_runtime.h>
#include <cuda_bf16.h>
#include <math.h>
#include <stdint.h>

// ============================================================================
// Problem constants
// ============================================================================
#define BATCH 4
#define CDIM  256
#define NTOK  4096
#define QKV_M (3 * CDIM)   // 768

// ============================================================================
// Device scratch (allocation-free: device globals)
// ============================================================================
__device__ float g_qkv[(size_t)BATCH * QKV_M * NTOK];       // 48 MB fp32
__device__ float g_S  [(size_t)BATCH * NTOK * NTOK];        // 256 MB fp32 (scores; later split-K partials)
__device__ float g_o  [(size_t)BATCH * CDIM * NTOK];        // 16 MB fp32

__device__ __nv_bfloat16 g_xT_h[(size_t)BATCH * NTOK * CDIM];
__device__ __nv_bfloat16 g_xT_l[(size_t)BATCH * NTOK * CDIM];
__device__ __nv_bfloat16 g_qT_h[(size_t)BATCH * NTOK * CDIM];
__device__ __nv_bfloat16 g_qT_l[(size_t)BATCH * NTOK * CDIM];
__device__ __nv_bfloat16 g_kT_h[(size_t)BATCH * NTOK * CDIM];
__device__ __nv_bfloat16 g_kT_l[(size_t)BATCH * NTOK * CDIM];
__device__ __nv_bfloat16 g_oT_h[(size_t)BATCH * NTOK * CDIM];
__device__ __nv_bfloat16 g_oT_l[(size_t)BATCH * NTOK * CDIM];
__device__ __nv_bfloat16 g_V_h [(size_t)BATCH * CDIM * NTOK];
__device__ __nv_bfloat16 g_V_l [(size_t)BATCH * CDIM * NTOK];
__device__ __nv_bfloat16 g_at_h[(size_t)BATCH * NTOK * NTOK];  // 128 MB
__device__ __nv_bfloat16 g_at_l[(size_t)BATCH * NTOK * NTOK];  // 128 MB
__device__ __nv_bfloat16 g_wq_h[QKV_M * CDIM];
__device__ __nv_bfloat16 g_wq_l[QKV_M * CDIM];
__device__ __nv_bfloat16 g_wo_h[CDIM * CDIM];
__device__ __nv_bfloat16 g_wo_l[CDIM * CDIM];

// ============================================================================
// Helpers (base sm_80-compatible: cp.async, ldmatrix, mma.sync)
// ============================================================================
__device__ __forceinline__ uint32_t smem_u32(const void* p) {
    uint32_t a;
    asm("{ .reg .u64 t; cvta.to.shared.u64 t, %1; cvt.u32.u64 %0, t; }" : "=r"(a) : "l"(p));
    return a;
}
__device__ __forceinline__ void cp_async16(uint32_t dst, const void* src) {
    asm volatile("cp.async.cg.shared.global [%0], [%1], 16;" :: "r"(dst), "l"(src));
}
#define CP_COMMIT() asm volatile("cp.async.commit_group;" ::: "memory")
#define CP_WAIT1()  asm volatile("cp.async.wait_group 1;" ::: "memory")

__device__ __forceinline__ void ldsm_x4(uint32_t& r0, uint32_t& r1, uint32_t& r2,
                                        uint32_t& r3, uint32_t addr) {
    asm volatile("ldmatrix.sync.aligned.m8n8.x4.shared.b16 {%0,%1,%2,%3}, [%4];"
                 : "=r"(r0), "=r"(r1), "=r"(r2), "=r"(r3) : "r"(addr));
}
__device__ __forceinline__ void mma16816(float* c, const uint32_t* a, const uint32_t* b) {
    asm volatile("mma.sync.aligned.m16n8k16.row.col.f32.bf16.bf16.f32 "
                 "{%0,%1,%2,%3}, {%4,%5,%6,%7}, {%8,%9}, {%0,%1,%2,%3};"
                 : "+f"(c[0]), "+f"(c[1]), "+f"(c[2]), "+f"(c[3])
                 : "r"(a[0]), "r"(a[1]), "r"(a[2]), "r"(a[3]), "r"(b[0]), "r"(b[1]));
}

// Swizzled smem offset for (row, c16) in a [rows][32 bf16] tile (64B rows)
__device__ __forceinline__ uint32_t swz(int row, int c16) {
    return (uint32_t)(row * 64 + ((c16 ^ ((row >> 1) & 3)) << 4));
}

// ============================================================================
// bf16x3 mma.sync GEMM (2-CTA-occupancy version):
//   D = alpha*( Ah.Bh + Ah.Bl + Al.Bh ) (+bias)
// A,B K-major bf16. M mult of 128, N mult of 64, Ksub mult of 32 (>= 64).
// Split-K: blockIdx.z = b*nsplit + s; writes slab zb of Cg.
// CTA tile 128x64, K-chunk 32, 3-stage cp.async (72 KB smem -> 2 CTAs/SM),
// 8 warps (4x2), warp tile 32x32, ~110 regs/thread.
// ============================================================================
#define A_TILE  8192                       // 128 rows * 64 B
#define B_TILE  4096                       // 64 rows * 64 B
#define STAGE_BYTES (2 * A_TILE + 2 * B_TILE)   // 24 KB
#define GSMEM   (3 * STAGE_BYTES)               // 72 KB

__device__ __forceinline__ void load_stage32(
    uint32_t stg, const __nv_bfloat16* Ah, const __nv_bfloat16* Al,
    const __nv_bfloat16* Bh, const __nv_bfloat16* Bl, int K, int k0, int tid)
{
    // 1536 16B-units: 512 Ah, 512 Al, 256 Bh, 256 Bl
    #pragma unroll
    for (int i = 0; i < 2; i++) {          // A units: tid + 256*i over 512
        int u = tid + 256 * i;
        int row = u >> 2, c16 = u & 3;
        uint32_t soff = swz(row, c16);
        size_t goff = (size_t)row * K + k0 + c16 * 8;
        cp_async16(stg + soff,          Ah + goff);
        cp_async16(stg + A_TILE + soff, Al + goff);
    }
    {                                       // B units: 256
        int u = tid;
        int row = u >> 2, c16 = u & 3;
        uint32_t soff = swz(row, c16);
        size_t goff = (size_t)row * K + k0 + c16 * 8;
        cp_async16(stg + 2 * A_TILE + soff,          Bh + goff);
        cp_async16(stg + 2 * A_TILE + B_TILE + soff, Bl + goff);
    }
}

__global__ __launch_bounds__(256, 2)
void gemm_bf16x3(const __nv_bfloat16* __restrict__ Ah, const __nv_bfloat16* __restrict__ Al, size_t Abs,
                 const __nv_bfloat16* __restrict__ Bh, const __nv_bfloat16* __restrict__ Bl, size_t Bbs,
                 float* __restrict__ Cg, size_t Cbs,
                 int M, int N, int K, int Ksub, int nsplit,
                 float alpha, const float* __restrict__ bias)
{
    extern __shared__ char smraw[];
    const uint32_t smb = smem_u32(smraw);

    const int tid = threadIdx.x;
    const int wid = tid >> 5, lane = tid & 31;
    const int wm = wid & 3;      // m warp 0..3 (32 rows)
    const int wn = wid >> 2;     // n warp 0..1 (32 cols)
    const int zb = blockIdx.z;
    const int b  = zb / nsplit;
    const int sp = zb % nsplit;
    const int koff = sp * Ksub;
    const int m0 = blockIdx.y * 128, n0 = blockIdx.x * 64;

    Ah += (size_t)b * Abs + (size_t)m0 * K + koff;
    Al += (size_t)b * Abs + (size_t)m0 * K + koff;
    Bh += (size_t)b * Bbs + (size_t)n0 * K + koff;
    Bl += (size_t)b * Bbs + (size_t)n0 * K + koff;
    float* Cp = Cg + (size_t)zb * Cbs;

    float acc[2][4][4];
    #pragma unroll
    for (int mt = 0; mt < 2; mt++)
        #pragma unroll
        for (int nt = 0; nt < 4; nt++)
            #pragma unroll
            for (int r = 0; r < 4; r++) acc[mt][nt][r] = 0.f;

    const int KC = Ksub / 32;

    // prologue: 2 stages in flight
    load_stage32(smb, Ah, Al, Bh, Bl, K, 0, tid);
    CP_COMMIT();
    load_stage32(smb + STAGE_BYTES, Ah, Al, Bh, Bl, K, 32, tid);
    CP_COMMIT();

    // lane geometry
    const int a_r = lane & 15;
    const int a_c = lane >> 4;
    const int b_r = (lane & 7) + (lane >> 4) * 8;
    const int b_c = (lane >> 3) & 1;

    for (int c = 0; c < KC; c++) {
        CP_WAIT1();
        __syncthreads();
        const uint32_t stg = smb + (uint32_t)(c % 3) * STAGE_BYTES;

        #pragma unroll
        for (int ks = 0; ks < 2; ks++) {
            uint32_t ahf[2][4], alf[2][4], bhf[4][2], blf[4][2];
            #pragma unroll
            for (int mt = 0; mt < 2; mt++) {
                int row = wm * 32 + mt * 16 + a_r;
                uint32_t off = swz(row, ks * 2 + a_c);
                ldsm_x4(ahf[mt][0], ahf[mt][1], ahf[mt][2], ahf[mt][3], stg + off);
                ldsm_x4(alf[mt][0], alf[mt][1], alf[mt][2], alf[mt][3], stg + A_TILE + off);
            }
            #pragma unroll
            for (int p = 0; p < 2; p++) {
                int row = wn * 32 + p * 16 + b_r;
                uint32_t off = swz(row, ks * 2 + b_c);
                ldsm_x4(bhf[2*p][0], bhf[2*p][1], bhf[2*p+1][0], bhf[2*p+1][1],
                        stg + 2 * A_TILE + off);
                ldsm_x4(blf[2*p][0], blf[2*p][1], blf[2*p+1][0], blf[2*p+1][1],
                        stg + 2 * A_TILE + B_TILE + off);
            }
            #pragma unroll
            for (int mt = 0; mt < 2; mt++)
                #pragma unroll
                for (int nt = 0; nt < 4; nt++) {
                    mma16816(acc[mt][nt], ahf[mt], bhf[nt]);
                    mma16816(acc[mt][nt], ahf[mt], blf[nt]);
                    mma16816(acc[mt][nt], alf[mt], bhf[nt]);
                }
        }

        if (c + 2 < KC)
            load_stage32(smb + (uint32_t)((c + 2) % 3) * STAGE_BYTES,
                         Ah, Al, Bh, Bl, K, (c + 2) * 32, tid);
        CP_COMMIT();
    }

    // Epilogue: direct fp32 float2 stores
    #pragma unroll
    for (int mt = 0; mt < 2; mt++) {
        const int row0 = m0 + wm * 32 + mt * 16 + (lane >> 2);
        const int row1 = row0 + 8;
        const float bv0 = bias ? bias[row0] : 0.f;
        const float bv1 = bias ? bias[row1] : 0.f;
        #pragma unroll
        for (int nt = 0; nt < 4; nt++) {
            const int col = n0 + wn * 32 + nt * 8 + (lane & 3) * 2;
            float2 v0 = make_float2(acc[mt][nt][0] * alpha + bv0,
                                    acc[mt][nt][1] * alpha + bv0);
            float2 v1 = make_float2(acc[mt][nt][2] * alpha + bv1,
                                    acc[mt][nt][3] * alpha + bv1);
            *(float2*)(Cp + (size_t)row0 * N + col) = v0;
            *(float2*)(Cp + (size_t)row1 * N + col) = v1;
        }
    }
}

// ============================================================================
// reduce4: out[b][i] = sum_{s<4} part[b*4+s][i]
// ============================================================================
__global__ __launch_bounds__(256)
void reduce4(const float* __restrict__ part, float* __restrict__ out, int n)
{
    const size_t b = blockIdx.z;
    const float4* p0 = (const float4*)(part + (b * 4 + 0) * (size_t)n);
    const float4* p1 = (const float4*)(part + (b * 4 + 1) * (size_t)n);
    const float4* p2 = (const float4*)(part + (b * 4 + 2) * (size_t)n);
    const float4* p3 = (const float4*)(part + (b * 4 + 3) * (size_t)n);
    float4* po = (float4*)(out + b * (size_t)n);
    const int n4 = n >> 2;
    for (int i = blockIdx.x * 256 + threadIdx.x; i < n4; i += gridDim.x * 256) {
        float4 a = p0[i], b1 = p1[i], c = p2[i], d = p3[i];
        po[i] = make_float4(a.x + b1.x + c.x + d.x, a.y + b1.y + c.y + d.y,
                            a.z + b1.z + c.z + d.z, a.w + b1.w + c.w + d.w);
    }
}

// ============================================================================
// split2d: f32 -> bf16 hi/lo (elementwise, z-batched)
// ============================================================================
__global__ __launch_bounds__(256)
void split2d(const float* __restrict__ in, size_t inStride,
             __nv_bfloat16* __restrict__ oh, __nv_bfloat16* __restrict__ ol,
             size_t oStride, int n)
{
    const size_t b = blockIdx.z;
    const float* p = in + b * inStride;
    __nv_bfloat16* ph = oh + b * oStride;
    __nv_bfloat16* pl = ol + b * oStride;
    for (int i = blockIdx.x * 256 + threadIdx.x; i < n; i += gridDim.x * 256) {
        float v = p[i];
        __nv_bfloat16 h = __float2bfloat16(v);
        ph[i] = h;
        pl[i] = __float2bfloat16(v - __bfloat162float(h));
    }
}

// ============================================================================
// transpose_split: f32 [R][Cl] -> bf16 hi/lo [Cl][R]  (z-batched)
// ============================================================================
__global__ __launch_bounds__(256)
void transpose_split(const float* __restrict__ in, size_t inStride,
                     __nv_bfloat16* __restrict__ oh, __nv_bfloat16* __restrict__ ol,
                     size_t oStride, int R, int Cl)
{
    __shared__ float t[32][33];
    const size_t b = blockIdx.z;
    const float* p = in + b * inStride;
    __nv_bfloat16* ph = oh + b * oStride;
    __nv_bfloat16* pl = ol + b * oStride;
    const int r0 = blockIdx.y * 32, c0 = blockIdx.x * 32;
    const int tx = threadIdx.x, ty = threadIdx.y;   // (32, 8)
    #pragma unroll
    for (int i = 0; i < 4; i++)
        t[ty + 8 * i][tx] = p[(size_t)(r0 + ty + 8 * i) * Cl + c0 + tx];
    __syncthreads();
    #pragma unroll
    for (int i = 0; i < 4; i++) {
        float v = t[tx][ty + 8 * i];
        __nv_bfloat16 h = __float2bfloat16(v);
        size_t o = (size_t)(c0 + ty + 8 * i) * R + r0 + tx;
        ph[o] = h;
        pl[o] = __float2bfloat16(v - __bfloat162float(h));
    }
}

// ============================================================================
// softmax rows of S (4096 wide) -> attn bf16 hi/lo
// ============================================================================
__global__ __launch_bounds__(256)
void softmax_split(const float* __restrict__ S,
                   __nv_bfloat16* __restrict__ ah, __nv_bfloat16* __restrict__ al)
{
    const size_t row = blockIdx.x;
    const float* p = S + row * (size_t)NTOK;
    __nv_bfloat16* ph = ah + row * (size_t)NTOK;
    __nv_bfloat16* pl = al + row * (size_t)NTOK;
    const int tid = threadIdx.x;

    float v[16];
    float mx = -1e30f;
    #pragma unroll
    for (int i = 0; i < 16; i++) {
        v[i] = p[tid + 256 * i];
        mx = fmaxf(mx, v[i]);
    }
    __shared__ float red[256];
    red[tid] = mx;
    __syncthreads();
    #pragma unroll
    for (int s = 128; s > 0; s >>= 1) {
        if (tid < s) red[tid] = fmaxf(red[tid], red[tid + s]);
        __syncthreads();
    }
    mx = red[0];
    __syncthreads();
    float sum = 0.f;
    #pragma unroll
    for (int i = 0; i < 16; i++) { v[i] = __expf(v[i] - mx); sum += v[i]; }
    red[tid] = sum;
    __syncthreads();
    #pragma unroll
    for (int s = 128; s > 0; s >>= 1) {
        if (tid < s) red[tid] += red[tid + s];
        __syncthreads();
    }
    const float inv = 1.0f / red[0];
    #pragma unroll
    for (int i = 0; i < 16; i++) {
        float a = v[i] * inv;
        __nv_bfloat16 h = __float2bfloat16(a);
        ph[tid + 256 * i] = h;
        pl[tid + 256 * i] = __float2bfloat16(a - __bfloat162float(h));
    }
}

// ============================================================================
// kernel_launch
// ============================================================================
extern "C" void kernel_launch(void* const* d_in, const int* in_sizes, int n_in,
                              void* d_out, int out_size)
{
    const float* x     = (const float*)d_in[0];
    const float* qkv_w = (const float*)d_in[1];
    const float* qkv_b = (const float*)d_in[2];
    const float* out_w = (const float*)d_in[3];
    const float* out_b = (const float*)d_in[4];
    float* out = (float*)d_out;

    cudaFuncSetAttribute(gemm_bf16x3, cudaFuncAttributeMaxDynamicSharedMemorySize, GSMEM);

    float *qkvp, *Sp, *op;
    __nv_bfloat16 *xTh, *xTl, *qTh, *qTl, *kTh, *kTl, *oTh, *oTl, *Vh, *Vl, *ath, *atl;
    __nv_bfloat16 *wqh, *wql, *woh, *wol;
    cudaGetSymbolAddress((void**)&qkvp, g_qkv);
    cudaGetSymbolAddress((void**)&Sp,  g_S);
    cudaGetSymbolAddress((void**)&op,  g_o);
    cudaGetSymbolAddress((void**)&xTh, g_xT_h); cudaGetSymbolAddress((void**)&xTl, g_xT_l);
    cudaGetSymbolAddress((void**)&qTh, g_qT_h); cudaGetSymbolAddress((void**)&qTl, g_qT_l);
    cudaGetSymbolAddress((void**)&kTh, g_kT_h); cudaGetSymbolAddress((void**)&kTl, g_kT_l);
    cudaGetSymbolAddress((void**)&oTh, g_oT_h); cudaGetSymbolAddress((void**)&oTl, g_oT_l);
    cudaGetSymbolAddress((void**)&Vh,  g_V_h);  cudaGetSymbolAddress((void**)&Vl,  g_V_l);
    cudaGetSymbolAddress((void**)&ath, g_at_h); cudaGetSymbolAddress((void**)&atl, g_at_l);
    cudaGetSymbolAddress((void**)&wqh, g_wq_h); cudaGetSymbolAddress((void**)&wql, g_wq_l);
    cudaGetSymbolAddress((void**)&woh, g_wo_h); cudaGetSymbolAddress((void**)&wol, g_wo_l);

    const size_t CN = (size_t)CDIM * NTOK;       // 1M
    const size_t NN = (size_t)NTOK * NTOK;       // 16M

    // --- weights split ---
    split2d<<<dim3(768, 1, 1), 256>>>(qkv_w, 0, wqh, wql, 0, QKV_M * CDIM);
    split2d<<<dim3(256, 1, 1), 256>>>(out_w, 0, woh, wol, 0, CDIM * CDIM);

    // --- xT (transpose+split): [4][256][4096] -> [4][4096][256]
    transpose_split<<<dim3(128, 8, BATCH), dim3(32, 8)>>>(x, CN, xTh, xTl, CN, CDIM, NTOK);

    // --- GEMM1: qkv[b][m=768][tok] = Wq @ x + b
    gemm_bf16x3<<<dim3(NTOK / 64, QKV_M / 128, BATCH), 256, GSMEM>>>(
        wqh, wql, 0, xTh, xTl, CN, qkvp, (size_t)QKV_M * NTOK,
        QKV_M, NTOK, CDIM, CDIM, 1, 1.0f, qkv_b);

    // --- transpose+split Q and K; split V
    transpose_split<<<dim3(128, 8, BATCH), dim3(32, 8)>>>(qkvp,      (size_t)QKV_M * NTOK, qTh, qTl, CN, CDIM, NTOK);
    transpose_split<<<dim3(128, 8, BATCH), dim3(32, 8)>>>(qkvp + CN, (size_t)QKV_M * NTOK, kTh, kTl, CN, CDIM, NTOK);
    split2d       <<<dim3(2048, 1, BATCH), 256>>>(qkvp + 2 * CN, (size_t)QKV_M * NTOK, Vh, Vl, CN, (int)CN);

    // --- GEMM2 (full 3-pass): S[b][m][n] = (qT . kT) / 16
    gemm_bf16x3<<<dim3(NTOK / 64, NTOK / 128, BATCH), 256, GSMEM>>>(
        qTh, qTl, CN, kTh, kTl, CN, Sp, NN,
        NTOK, NTOK, CDIM, CDIM, 1, 0.0625f, nullptr);

    // --- softmax rows -> attn hi/lo
    softmax_split<<<BATCH * NTOK, 256>>>(Sp, ath, atl);

    // --- GEMM3 (split-K=4, exact): partials into g_S slabs [b*4+s][256][4096]
    gemm_bf16x3<<<dim3(NTOK / 64, CDIM / 128, BATCH * 4), 256, GSMEM>>>(
        Vh, Vl, CN, ath, atl, NN, Sp, CN,
        CDIM, NTOK, NTOK, NTOK / 4, 4, 1.0f, nullptr);

    // --- reduce split-K partials -> O[b][c][m]
    reduce4<<<dim3(512, 1, BATCH), 256>>>(Sp, op, (int)CN);

    // --- transpose+split O -> oT
    transpose_split<<<dim3(128, 8, BATCH), dim3(32, 8)>>>(op, CN, oTh, oTl, CN, CDIM, NTOK);

    // --- GEMM4: out[b][o][tok] = Wo @ O + b
    gemm_bf16x3<<<dim3(NTOK / 64, CDIM / 128, BATCH), 256, GSMEM>>>(
        woh, wol, 0, oTh, oTl, CN, out, CN,
        CDIM, NTOK, CDIM, CDIM, 1, 1.0f, out_b);
}

// round 14
// speedup vs baseline: 1.1301x; 1.1301x over previous
#include <cuda_runtime.h>
#include <cuda_fp16.h>
#include <math.h>
#include <stdint.h>

// ============================================================================
// Problem constants
// ============================================================================
#define BATCH 4
#define CDIM  256
#define NTOK  4096
#define QKV_M (3 * CDIM)   // 768

// ============================================================================
// Device scratch (allocation-free: device globals)
// ============================================================================
__device__ float g_qkv[(size_t)BATCH * QKV_M * NTOK];       // 48 MB fp32
__device__ float g_S  [(size_t)BATCH * NTOK * NTOK];        // 256 MB fp32 (scores; later split-K partials)
__device__ float g_o  [(size_t)BATCH * CDIM * NTOK];        // 16 MB fp32

__device__ __half g_xT_h[(size_t)BATCH * NTOK * CDIM];
__device__ __half g_xT_l[(size_t)BATCH * NTOK * CDIM];
__device__ __half g_qT_h[(size_t)BATCH * NTOK * CDIM];
__device__ __half g_qT_l[(size_t)BATCH * NTOK * CDIM];
__device__ __half g_kT_h[(size_t)BATCH * NTOK * CDIM];
__device__ __half g_kT_l[(size_t)BATCH * NTOK * CDIM];
__device__ __half g_oT_h[(size_t)BATCH * NTOK * CDIM];
__device__ __half g_oT_l[(size_t)BATCH * NTOK * CDIM];
__device__ __half g_V_h [(size_t)BATCH * CDIM * NTOK];
__device__ __half g_V_l [(size_t)BATCH * CDIM * NTOK];
__device__ __half g_at_h[(size_t)BATCH * NTOK * NTOK];  // 128 MB
__device__ __half g_at_l[(size_t)BATCH * NTOK * NTOK];  // 128 MB
__device__ __half g_wq_h[QKV_M * CDIM];
__device__ __half g_wq_l[QKV_M * CDIM];
__device__ __half g_wo_h[CDIM * CDIM];
__device__ __half g_wo_l[CDIM * CDIM];

// ============================================================================
// Helpers (base sm_80-compatible: cp.async, ldmatrix, mma.sync)
// ============================================================================
__device__ __forceinline__ uint32_t smem_u32(const void* p) {
    uint32_t a;
    asm("{ .reg .u64 t; cvta.to.shared.u64 t, %1; cvt.u32.u64 %0, t; }" : "=r"(a) : "l"(p));
    return a;
}
__device__ __forceinline__ void cp_async16(uint32_t dst, const void* src) {
    asm volatile("cp.async.cg.shared.global [%0], [%1], 16;" :: "r"(dst), "l"(src));
}
#define CP_COMMIT() asm volatile("cp.async.commit_group;" ::: "memory")
#define CP_WAIT1()  asm volatile("cp.async.wait_group 1;" ::: "memory")

__device__ __forceinline__ void ldsm_x4(uint32_t& r0, uint32_t& r1, uint32_t& r2,
                                        uint32_t& r3, uint32_t addr) {
    asm volatile("ldmatrix.sync.aligned.m8n8.x4.shared.b16 {%0,%1,%2,%3}, [%4];"
                 : "=r"(r0), "=r"(r1), "=r"(r2), "=r"(r3) : "r"(addr));
}
__device__ __forceinline__ void mma16816(float* c, const uint32_t* a, const uint32_t* b) {
    asm volatile("mma.sync.aligned.m16n8k16.row.col.f32.f16.f16.f32 "
                 "{%0,%1,%2,%3}, {%4,%5,%6,%7}, {%8,%9}, {%0,%1,%2,%3};"
                 : "+f"(c[0]), "+f"(c[1]), "+f"(c[2]), "+f"(c[3])
                 : "r"(a[0]), "r"(a[1]), "r"(a[2]), "r"(a[3]), "r"(b[0]), "r"(b[1]));
}

// SW128 swizzled offset for (row, c16) in a [rows][64 half] tile (128B rows)
__device__ __forceinline__ uint32_t swz128(int row, int c16) {
    return (uint32_t)(row * 128 + ((c16 ^ (row & 7)) << 4));
}

// ============================================================================
// fp16 multi-pass mma.sync GEMM:
//   PASSES==3: D = alpha*( Ah.Bh + Ah.Bl + Al.Bh ) (+bias)
//   PASSES==2: D = alpha*( Ah.Bh + Ah.Bl )         (+bias)  [A-lo never loaded]
// A,B K-major fp16. M,N mult of 128, Ksub mult of 64 (>= 128).
// Split-K: blockIdx.z = b*nsplit + s; writes slab zb of Cg.
// CTA 128x128, K-chunk 64, 3-stage cp.async, 8 warps (4x2), warp 32x64,
// register double-buffered k16-step pipeline.
// ============================================================================
#define TILE_BYTES  16384                 // 128 rows * 128 B
#define STAGE_BYTES (4 * TILE_BYTES)      // Ah, Al, Bh, Bl slots
#define GSMEM       (3 * STAGE_BYTES)     // 192 KB

template<int PASSES>
__device__ __forceinline__ void load_stage64(
    uint32_t stg, const __half* Ah, const __half* Al,
    const __half* Bh, const __half* Bl, int K, int k0, int tid)
{
    #pragma unroll
    for (int i = 0; i < 4; i++) {
        int idx = tid + 256 * i;          // 0..1023
        int row = idx >> 3;               // 0..127
        int c16 = idx & 7;                // 0..7
        uint32_t soff = swz128(row, c16);
        size_t goff = (size_t)row * K + k0 + c16 * 8;
        cp_async16(stg + 0 * TILE_BYTES + soff, Ah + goff);
        if (PASSES == 3)
            cp_async16(stg + 1 * TILE_BYTES + soff, Al + goff);
        cp_async16(stg + 2 * TILE_BYTES + soff, Bh + goff);
        cp_async16(stg + 3 * TILE_BYTES + soff, Bl + goff);
    }
}

template<int PASSES>
__global__ __launch_bounds__(256, 1)
void gemm_f16mp(const __half* __restrict__ Ah, const __half* __restrict__ Al, size_t Abs,
                const __half* __restrict__ Bh, const __half* __restrict__ Bl, size_t Bbs,
                float* __restrict__ Cg, size_t Cbs,
                int M, int N, int K, int Ksub, int nsplit,
                float alpha, const float* __restrict__ bias)
{
    extern __shared__ char smraw[];
    const uint32_t smb = smem_u32(smraw);

    const int tid = threadIdx.x;
    const int wid = tid >> 5, lane = tid & 31;
    const int wm = wid & 3;      // m warp 0..3 (32 rows)
    const int wn = wid >> 2;     // n warp 0..1 (64 cols)
    const int zb = blockIdx.z;
    const int b  = zb / nsplit;
    const int sp = zb % nsplit;
    const int koff = sp * Ksub;
    const int m0 = blockIdx.y * 128, n0 = blockIdx.x * 128;

    Ah += (size_t)b * Abs + (size_t)m0 * K + koff;
    Al += (size_t)b * Abs + (size_t)m0 * K + koff;
    Bh += (size_t)b * Bbs + (size_t)n0 * K + koff;
    Bl += (size_t)b * Bbs + (size_t)n0 * K + koff;
    float* Cp = Cg + (size_t)zb * Cbs;

    float acc[2][8][4];
    #pragma unroll
    for (int mt = 0; mt < 2; mt++)
        #pragma unroll
        for (int nt = 0; nt < 8; nt++)
            #pragma unroll
            for (int r = 0; r < 4; r++) acc[mt][nt][r] = 0.f;

    const int KC = Ksub / 64;

    // prologue: 2 stages in flight
    load_stage64<PASSES>(smb, Ah, Al, Bh, Bl, K, 0, tid);
    CP_COMMIT();
    load_stage64<PASSES>(smb + STAGE_BYTES, Ah, Al, Bh, Bl, K, 64, tid);
    CP_COMMIT();

    // lane geometry
    const int a_r = lane & 15;
    const int a_c = lane >> 4;
    const int b_r = (lane & 7) + (lane >> 4) * 8;
    const int b_c = (lane >> 3) & 1;

    uint32_t ahf[2][2][4], alf[2][2][4], bhf[2][8][2], blf[2][8][2];

    for (int c = 0; c < KC; c++) {
        CP_WAIT1();
        __syncthreads();
        const uint32_t stg = smb + (uint32_t)(c % 3) * STAGE_BYTES;

        // fragments for k-step 0 -> buffer 0
        {
            #pragma unroll
            for (int mt = 0; mt < 2; mt++) {
                int row = wm * 32 + mt * 16 + a_r;
                uint32_t off = swz128(row, a_c);
                ldsm_x4(ahf[0][mt][0], ahf[0][mt][1], ahf[0][mt][2], ahf[0][mt][3],
                        stg + off);
                if (PASSES == 3)
                    ldsm_x4(alf[0][mt][0], alf[0][mt][1], alf[0][mt][2], alf[0][mt][3],
                            stg + TILE_BYTES + off);
            }
            #pragma unroll
            for (int p = 0; p < 4; p++) {
                int row = wn * 64 + p * 16 + b_r;
                uint32_t off = swz128(row, b_c);
                ldsm_x4(bhf[0][2*p][0], bhf[0][2*p][1], bhf[0][2*p+1][0], bhf[0][2*p+1][1],
                        stg + 2 * TILE_BYTES + off);
                ldsm_x4(blf[0][2*p][0], blf[0][2*p][1], blf[0][2*p+1][0], blf[0][2*p+1][1],
                        stg + 3 * TILE_BYTES + off);
            }
        }

        #pragma unroll
        for (int ks = 0; ks < 4; ks++) {
            const int cur = ks & 1, nxt = cur ^ 1;
            if (ks < 3) {
                // prefetch next k-step fragments (hidden under MMA burst)
                #pragma unroll
                for (int mt = 0; mt < 2; mt++) {
                    int row = wm * 32 + mt * 16 + a_r;
                    uint32_t off = swz128(row, (ks + 1) * 2 + a_c);
                    ldsm_x4(ahf[nxt][mt][0], ahf[nxt][mt][1], ahf[nxt][mt][2], ahf[nxt][mt][3],
                            stg + off);
                    if (PASSES == 3)
                        ldsm_x4(alf[nxt][mt][0], alf[nxt][mt][1], alf[nxt][mt][2], alf[nxt][mt][3],
                                stg + TILE_BYTES + off);
                }
                #pragma unroll
                for (int p = 0; p < 4; p++) {
                    int row = wn * 64 + p * 16 + b_r;
                    uint32_t off = swz128(row, (ks + 1) * 2 + b_c);
                    ldsm_x4(bhf[nxt][2*p][0], bhf[nxt][2*p][1], bhf[nxt][2*p+1][0], bhf[nxt][2*p+1][1],
                            stg + 2 * TILE_BYTES + off);
                    ldsm_x4(blf[nxt][2*p][0], blf[nxt][2*p][1], blf[nxt][2*p+1][0], blf[nxt][2*p+1][1],
                            stg + 3 * TILE_BYTES + off);
                }
            }
            #pragma unroll
            for (int mt = 0; mt < 2; mt++)
                #pragma unroll
                for (int nt = 0; nt < 8; nt++) {
                    mma16816(acc[mt][nt], ahf[cur][mt], bhf[cur][nt]);
                    mma16816(acc[mt][nt], ahf[cur][mt], blf[cur][nt]);
                    if (PASSES == 3)
                        mma16816(acc[mt][nt], alf[cur][mt], bhf[cur][nt]);
                }
        }

        if (c + 2 < KC)
            load_stage64<PASSES>(smb + (uint32_t)((c + 2) % 3) * STAGE_BYTES,
                                 Ah, Al, Bh, Bl, K, (c + 2) * 64, tid);
        CP_COMMIT();
    }

    // Epilogue: direct fp32 float2 stores
    #pragma unroll
    for (int mt = 0; mt < 2; mt++) {
        const int row0 = m0 + wm * 32 + mt * 16 + (lane >> 2);
        const int row1 = row0 + 8;
        const float bv0 = bias ? bias[row0] : 0.f;
        const float bv1 = bias ? bias[row1] : 0.f;
        #pragma unroll
        for (int nt = 0; nt < 8; nt++) {
            const int col = n0 + wn * 64 + nt * 8 + (lane & 3) * 2;
            float2 v0 = make_float2(acc[mt][nt][0] * alpha + bv0,
                                    acc[mt][nt][1] * alpha + bv0);
            float2 v1 = make_float2(acc[mt][nt][2] * alpha + bv1,
                                    acc[mt][nt][3] * alpha + bv1);
            *(float2*)(Cp + (size_t)row0 * N + col) = v0;
            *(float2*)(Cp + (size_t)row1 * N + col) = v1;
        }
    }
}

// ============================================================================
// reduce4: out[b][i] = sum_{s<4} part[b*4+s][i]
// ============================================================================
__global__ __launch_bounds__(256)
void reduce4(const float* __restrict__ part, float* __restrict__ out, int n)
{
    const size_t b = blockIdx.z;
    const float4* p0 = (const float4*)(part + (b * 4 + 0) * (size_t)n);
    const float4* p1 = (const float4*)(part + (b * 4 + 1) * (size_t)n);
    const float4* p2 = (const float4*)(part + (b * 4 + 2) * (size_t)n);
    const float4* p3 = (const float4*)(part + (b * 4 + 3) * (size_t)n);
    float4* po = (float4*)(out + b * (size_t)n);
    const int n4 = n >> 2;
    for (int i = blockIdx.x * 256 + threadIdx.x; i < n4; i += gridDim.x * 256) {
        float4 a = p0[i], b1 = p1[i], c = p2[i], d = p3[i];
        po[i] = make_float4(a.x + b1.x + c.x + d.x, a.y + b1.y + c.y + d.y,
                            a.z + b1.z + c.z + d.z, a.w + b1.w + c.w + d.w);
    }
}

// ============================================================================
// split2d: f32 -> fp16 hi/lo (elementwise, z-batched)
// ============================================================================
__global__ __launch_bounds__(256)
void split2d(const float* __restrict__ in, size_t inStride,
             __half* __restrict__ oh, __half* __restrict__ ol,
             size_t oStride, int n)
{
    const size_t b = blockIdx.z;
    const float* p = in + b * inStride;
    __half* ph = oh + b * oStride;
    __half* pl = ol + b * oStride;
    for (int i = blockIdx.x * 256 + threadIdx.x; i < n; i += gridDim.x * 256) {
        float v = p[i];
        __half h = __float2half_rn(v);
        ph[i] = h;
        pl[i] = __float2half_rn(v - __half2float(h));
    }
}

// ============================================================================
// transpose_split: f32 [R][Cl] -> fp16 hi/lo [Cl][R]  (z-batched)
// ============================================================================
__global__ __launch_bounds__(256)
void transpose_split(const float* __restrict__ in, size_t inStride,
                     __half* __restrict__ oh, __half* __restrict__ ol,
                     size_t oStride, int R, int Cl)
{
    __shared__ float t[32][33];
    const size_t b = blockIdx.z;
    const float* p = in + b * inStride;
    __half* ph = oh + b * oStride;
    __half* pl = ol + b * oStride;
    const int r0 = blockIdx.y * 32, c0 = blockIdx.x * 32;
    const int tx = threadIdx.x, ty = threadIdx.y;   // (32, 8)
    #pragma unroll
    for (int i = 0; i < 4; i++)
        t[ty + 8 * i][tx] = p[(size_t)(r0 + ty + 8 * i) * Cl + c0 + tx];
    __syncthreads();
    #pragma unroll
    for (int i = 0; i < 4; i++) {
        float v = t[tx][ty + 8 * i];
        __half h = __float2half_rn(v);
        size_t o = (size_t)(c0 + ty + 8 * i) * R + r0 + tx;
        ph[o] = h;
        pl[o] = __float2half_rn(v - __half2float(h));
    }
}

// ============================================================================
// softmax rows of S (4096 wide) -> attn fp16 hi/lo
// ============================================================================
__global__ __launch_bounds__(256)
void softmax_split(const float* __restrict__ S,
                   __half* __restrict__ ah, __half* __restrict__ al)
{
    const size_t row = blockIdx.x;
    const float* p = S + row * (size_t)NTOK;
    __half* ph = ah + row * (size_t)NTOK;
    __half* pl = al + row * (size_t)NTOK;
    const int tid = threadIdx.x;

    float v[16];
    float mx = -1e30f;
    #pragma unroll
    for (int i = 0; i < 16; i++) {
        v[i] = p[tid + 256 * i];
        mx = fmaxf(mx, v[i]);
    }
    __shared__ float red[256];
    red[tid] = mx;
    __syncthreads();
    #pragma unroll
    for (int s = 128; s > 0; s >>= 1) {
        if (tid < s) red[tid] = fmaxf(red[tid], red[tid + s]);
        __syncthreads();
    }
    mx = red[0];
    __syncthreads();
    float sum = 0.f;
    #pragma unroll
    for (int i = 0; i < 16; i++) { v[i] = __expf(v[i] - mx); sum += v[i]; }
    red[tid] = sum;
    __syncthreads();
    #pragma unroll
    for (int s = 128; s > 0; s >>= 1) {
        if (tid < s) red[tid] += red[tid + s];
        __syncthreads();
    }
    const float inv = 1.0f / red[0];
    #pragma unroll
    for (int i = 0; i < 16; i++) {
        float a = v[i] * inv;
        __half h = __float2half_rn(a);
        ph[tid + 256 * i] = h;
        pl[tid + 256 * i] = __float2half_rn(a - __half2float(h));
    }
}

// ============================================================================
// kernel_launch
// ============================================================================
extern "C" void kernel_launch(void* const* d_in, const int* in_sizes, int n_in,
                              void* d_out, int out_size)
{
    const float* x     = (const float*)d_in[0];
    const float* qkv_w = (const float*)d_in[1];
    const float* qkv_b = (const float*)d_in[2];
    const float* out_w = (const float*)d_in[3];
    const float* out_b = (const float*)d_in[4];
    float* out = (float*)d_out;

    cudaFuncSetAttribute(gemm_f16mp<3>, cudaFuncAttributeMaxDynamicSharedMemorySize, GSMEM);
    cudaFuncSetAttribute(gemm_f16mp<2>, cudaFuncAttributeMaxDynamicSharedMemorySize, GSMEM);

    float *qkvp, *Sp, *op;
    __half *xTh, *xTl, *qTh, *qTl, *kTh, *kTl, *oTh, *oTl, *Vh, *Vl, *ath, *atl;
    __half *wqh, *wql, *woh, *wol;
    cudaGetSymbolAddress((void**)&qkvp, g_qkv);
    cudaGetSymbolAddress((void**)&Sp,  g_S);
    cudaGetSymbolAddress((void**)&op,  g_o);
    cudaGetSymbolAddress((void**)&xTh, g_xT_h); cudaGetSymbolAddress((void**)&xTl, g_xT_l);
    cudaGetSymbolAddress((void**)&qTh, g_qT_h); cudaGetSymbolAddress((void**)&qTl, g_qT_l);
    cudaGetSymbolAddress((void**)&kTh, g_kT_h); cudaGetSymbolAddress((void**)&kTl, g_kT_l);
    cudaGetSymbolAddress((void**)&oTh, g_oT_h); cudaGetSymbolAddress((void**)&oTl, g_oT_l);
    cudaGetSymbolAddress((void**)&Vh,  g_V_h);  cudaGetSymbolAddress((void**)&Vl,  g_V_l);
    cudaGetSymbolAddress((void**)&ath, g_at_h); cudaGetSymbolAddress((void**)&atl, g_at_l);
    cudaGetSymbolAddress((void**)&wqh, g_wq_h); cudaGetSymbolAddress((void**)&wql, g_wq_l);
    cudaGetSymbolAddress((void**)&woh, g_wo_h); cudaGetSymbolAddress((void**)&wol, g_wo_l);

    const size_t CN = (size_t)CDIM * NTOK;       // 1M
    const size_t NN = (size_t)NTOK * NTOK;       // 16M

    // --- weights split ---
    split2d<<<dim3(768, 1, 1), 256>>>(qkv_w, 0, wqh, wql, 0, QKV_M * CDIM);
    split2d<<<dim3(256, 1, 1), 256>>>(out_w, 0, woh, wol, 0, CDIM * CDIM);

    // --- xT (transpose+split): [4][256][4096] -> [4][4096][256]
    transpose_split<<<dim3(128, 8, BATCH), dim3(32, 8)>>>(x, CN, xTh, xTl, CN, CDIM, NTOK);

    // --- GEMM1 (3-pass): qkv[b][m=768][tok] = Wq @ x + b
    gemm_f16mp<3><<<dim3(NTOK / 128, QKV_M / 128, BATCH), 256, GSMEM>>>(
        wqh, wql, 0, xTh, xTl, CN, qkvp, (size_t)QKV_M * NTOK,
        QKV_M, NTOK, CDIM, CDIM, 1, 1.0f, qkv_b);

    // --- transpose+split Q and K; split V
    transpose_split<<<dim3(128, 8, BATCH), dim3(32, 8)>>>(qkvp,      (size_t)QKV_M * NTOK, qTh, qTl, CN, CDIM, NTOK);
    transpose_split<<<dim3(128, 8, BATCH), dim3(32, 8)>>>(qkvp + CN, (size_t)QKV_M * NTOK, kTh, kTl, CN, CDIM, NTOK);
    split2d       <<<dim3(2048, 1, BATCH), 256>>>(qkvp + 2 * CN, (size_t)QKV_M * NTOK, Vh, Vl, CN, (int)CN);

    // --- GEMM2 (fp16 2-pass: qh.(kh+kl)): S[b][m][n] = (qT . kT) / 16
    gemm_f16mp<2><<<dim3(NTOK / 128, NTOK / 128, BATCH), 256, GSMEM>>>(
        qTh, qTl, CN, kTh, kTl, CN, Sp, NN,
        NTOK, NTOK, CDIM, CDIM, 1, 0.0625f, nullptr);

    // --- softmax rows -> attn hi/lo
    softmax_split<<<BATCH * NTOK, 256>>>(Sp, ath, atl);

    // --- GEMM3 (3-pass, split-K=4, exact): partials into g_S slabs
    gemm_f16mp<3><<<dim3(NTOK / 128, CDIM / 128, BATCH * 4), 256, GSMEM>>>(
        Vh, Vl, CN, ath, atl, NN, Sp, CN,
        CDIM, NTOK, NTOK, NTOK / 4, 4, 1.0f, nullptr);

    // --- reduce split-K partials -> O[b][c][m]
    reduce4<<<dim3(512, 1, BATCH), 256>>>(Sp, op, (int)CN);

    // --- transpose+split O -> oT
    transpose_split<<<dim3(128, 8, BATCH), dim3(32, 8)>>>(op, CN, oTh, oTl, CN, CDIM, NTOK);

    // --- GEMM4 (3-pass): out[b][o][tok] = Wo @ O + b
    gemm_f16mp<3><<<dim3(NTOK / 128, CDIM / 128, BATCH), 256, GSMEM>>>(
        woh, wol, 0, oTh, oTl, CN, out, CN,
        CDIM, NTOK, CDIM, CDIM, 1, 1.0f, out_b);
}

// round 17
// speedup vs baseline: 1.2965x; 1.1472x over previous
#include <cuda_runtime.h>
#include <cuda_fp16.h>
#include <math.h>
#include <stdint.h>

// ============================================================================
// Problem constants
// ============================================================================
#define BATCH 4
#define CDIM  256
#define NTOK  4096
#define QKV_M (3 * CDIM)   // 768

// ============================================================================
// Device scratch (allocation-free: device globals)
// ============================================================================
__device__ float g_qkv[(size_t)BATCH * QKV_M * NTOK];       // 48 MB fp32
__device__ float g_S  [(size_t)BATCH * NTOK * NTOK];        // 256 MB fp32 (scores; later split-K partials)
__device__ float g_o  [(size_t)BATCH * CDIM * NTOK];        // 16 MB fp32

__device__ __half g_xT_h[(size_t)BATCH * NTOK * CDIM];
__device__ __half g_xT_l[(size_t)BATCH * NTOK * CDIM];
__device__ __half g_qT_h[(size_t)BATCH * NTOK * CDIM];
__device__ __half g_qT_l[(size_t)BATCH * NTOK * CDIM];
__device__ __half g_kT_h[(size_t)BATCH * NTOK * CDIM];
__device__ __half g_kT_l[(size_t)BATCH * NTOK * CDIM];
__device__ __half g_oT_h[(size_t)BATCH * NTOK * CDIM];
__device__ __half g_oT_l[(size_t)BATCH * NTOK * CDIM];
__device__ __half g_V_h [(size_t)BATCH * CDIM * NTOK];
__device__ __half g_V_l [(size_t)BATCH * CDIM * NTOK];
__device__ __half g_at_h[(size_t)BATCH * NTOK * NTOK];  // 128 MB (attn hi only)
__device__ __half g_wq_h[QKV_M * CDIM];
__device__ __half g_wq_l[QKV_M * CDIM];
__device__ __half g_wo_h[CDIM * CDIM];
__device__ __half g_wo_l[CDIM * CDIM];

// ============================================================================
// Helpers (base sm_80-compatible: cp.async, ldmatrix, mma.sync)
// ============================================================================
__device__ __forceinline__ uint32_t smem_u32(const void* p) {
    uint32_t a;
    asm("{ .reg .u64 t; cvta.to.shared.u64 t, %1; cvt.u32.u64 %0, t; }" : "=r"(a) : "l"(p));
    return a;
}
__device__ __forceinline__ void cp_async16(uint32_t dst, const void* src) {
    asm volatile("cp.async.cg.shared.global [%0], [%1], 16;" :: "r"(dst), "l"(src));
}
#define CP_COMMIT() asm volatile("cp.async.commit_group;" ::: "memory")
#define CP_WAIT1()  asm volatile("cp.async.wait_group 1;" ::: "memory")

__device__ __forceinline__ void ldsm_x4(uint32_t& r0, uint32_t& r1, uint32_t& r2,
                                        uint32_t& r3, uint32_t addr) {
    asm volatile("ldmatrix.sync.aligned.m8n8.x4.shared.b16 {%0,%1,%2,%3}, [%4];"
                 : "=r"(r0), "=r"(r1), "=r"(r2), "=r"(r3) : "r"(addr));
}
__device__ __forceinline__ void mma16816(float* c, const uint32_t* a, const uint32_t* b) {
    asm volatile("mma.sync.aligned.m16n8k16.row.col.f32.f16.f16.f32 "
                 "{%0,%1,%2,%3}, {%4,%5,%6,%7}, {%8,%9}, {%0,%1,%2,%3};"
                 : "+f"(c[0]), "+f"(c[1]), "+f"(c[2]), "+f"(c[3])
                 : "r"(a[0]), "r"(a[1]), "r"(a[2]), "r"(a[3]), "r"(b[0]), "r"(b[1]));
}

// SW128 swizzled offset for (row, c16) in a [rows][64 half] tile (128B rows)
__device__ __forceinline__ uint32_t swz128(int row, int c16) {
    return (uint32_t)(row * 128 + ((c16 ^ (row & 7)) << 4));
}

// ============================================================================
// fp16 multi-pass mma.sync GEMM:
//   MODE==0: D = alpha*( Ah.Bh + Ah.Bl + Al.Bh ) (+bias)   [full 3-pass]
//   MODE==1: D = alpha*( Ah.Bh + Ah.Bl )         (+bias)   [A-lo dropped]
//   MODE==2: D = alpha*( Ah.Bh + Al.Bh )         (+bias)   [B-lo dropped; Bl may be null]
// A,B K-major fp16. M,N mult of 128, Ksub mult of 64 (>= 128).
// Split-K: blockIdx.z = b*nsplit + s; writes slab zb of Cg.
// CTA 128x128, K-chunk 64, 3-stage cp.async, 8 warps (4x2), warp 32x64,
// register double-buffered k16-step pipeline.
// ============================================================================
#define TILE_BYTES  16384                 // 128 rows * 128 B
#define STAGE_BYTES (4 * TILE_BYTES)      // Ah, Al, Bh, Bl slots
#define GSMEM       (3 * STAGE_BYTES)     // 192 KB

template<int MODE>
__device__ __forceinline__ void load_stage64(
    uint32_t stg, const __half* Ah, const __half* Al,
    const __half* Bh, const __half* Bl, int K, int k0, int tid)
{
    #pragma unroll
    for (int i = 0; i < 4; i++) {
        int idx = tid + 256 * i;          // 0..1023
        int row = idx >> 3;               // 0..127
        int c16 = idx & 7;                // 0..7
        uint32_t soff = swz128(row, c16);
        size_t goff = (size_t)row * K + k0 + c16 * 8;
        cp_async16(stg + 0 * TILE_BYTES + soff, Ah + goff);
        if (MODE != 1)
            cp_async16(stg + 1 * TILE_BYTES + soff, Al + goff);
        cp_async16(stg + 2 * TILE_BYTES + soff, Bh + goff);
        if (MODE != 2)
            cp_async16(stg + 3 * TILE_BYTES + soff, Bl + goff);
    }
}

template<int MODE>
__global__ __launch_bounds__(256, 1)
void gemm_f16mp(const __half* __restrict__ Ah, const __half* __restrict__ Al, size_t Abs,
                const __half* __restrict__ Bh, const __half* __restrict__ Bl, size_t Bbs,
                float* __restrict__ Cg, size_t Cbs,
                int M, int N, int K, int Ksub, int nsplit,
                float alpha, const float* __restrict__ bias)
{
    extern __shared__ char smraw[];
    const uint32_t smb = smem_u32(smraw);

    const int tid = threadIdx.x;
    const int wid = tid >> 5, lane = tid & 31;
    const int wm = wid & 3;      // m warp 0..3 (32 rows)
    const int wn = wid >> 2;     // n warp 0..1 (64 cols)
    const int zb = blockIdx.z;
    const int b  = zb / nsplit;
    const int sp = zb % nsplit;
    const int koff = sp * Ksub;
    const int m0 = blockIdx.y * 128, n0 = blockIdx.x * 128;

    Ah += (size_t)b * Abs + (size_t)m0 * K + koff;
    Al += (size_t)b * Abs + (size_t)m0 * K + koff;
    Bh += (size_t)b * Bbs + (size_t)n0 * K + koff;
    if (MODE != 2) Bl += (size_t)b * Bbs + (size_t)n0 * K + koff;
    float* Cp = Cg + (size_t)zb * Cbs;

    float acc[2][8][4];
    #pragma unroll
    for (int mt = 0; mt < 2; mt++)
        #pragma unroll
        for (int nt = 0; nt < 8; nt++)
            #pragma unroll
            for (int r = 0; r < 4; r++) acc[mt][nt][r] = 0.f;

    const int KC = Ksub / 64;

    // prologue: 2 stages in flight
    load_stage64<MODE>(smb, Ah, Al, Bh, Bl, K, 0, tid);
    CP_COMMIT();
    load_stage64<MODE>(smb + STAGE_BYTES, Ah, Al, Bh, Bl, K, 64, tid);
    CP_COMMIT();

    // lane geometry
    const int a_r = lane & 15;
    const int a_c = lane >> 4;
    const int b_r = (lane & 7) + (lane >> 4) * 8;
    const int b_c = (lane >> 3) & 1;

    uint32_t ahf[2][2][4], alf[2][2][4], bhf[2][8][2], blf[2][8][2];

    for (int c = 0; c < KC; c++) {
        CP_WAIT1();
        __syncthreads();
        const uint32_t stg = smb + (uint32_t)(c % 3) * STAGE_BYTES;

        // fragments for k-step 0 -> buffer 0
        {
            #pragma unroll
            for (int mt = 0; mt < 2; mt++) {
                int row = wm * 32 + mt * 16 + a_r;
                uint32_t off = swz128(row, a_c);
                ldsm_x4(ahf[0][mt][0], ahf[0][mt][1], ahf[0][mt][2], ahf[0][mt][3],
                        stg + off);
                if (MODE != 1)
                    ldsm_x4(alf[0][mt][0], alf[0][mt][1], alf[0][mt][2], alf[0][mt][3],
                            stg + TILE_BYTES + off);
            }
            #pragma unroll
            for (int p = 0; p < 4; p++) {
                int row = wn * 64 + p * 16 + b_r;
                uint32_t off = swz128(row, b_c);
                ldsm_x4(bhf[0][2*p][0], bhf[0][2*p][1], bhf[0][2*p+1][0], bhf[0][2*p+1][1],
                        stg + 2 * TILE_BYTES + off);
                if (MODE != 2)
                    ldsm_x4(blf[0][2*p][0], blf[0][2*p][1], blf[0][2*p+1][0], blf[0][2*p+1][1],
                            stg + 3 * TILE_BYTES + off);
            }
        }

        #pragma unroll
        for (int ks = 0; ks < 4; ks++) {
            const int cur = ks & 1, nxt = cur ^ 1;
            if (ks < 3) {
                // prefetch next k-step fragments (hidden under MMA burst)
                #pragma unroll
                for (int mt = 0; mt < 2; mt++) {
                    int row = wm * 32 + mt * 16 + a_r;
                    uint32_t off = swz128(row, (ks + 1) * 2 + a_c);
                    ldsm_x4(ahf[nxt][mt][0], ahf[nxt][mt][1], ahf[nxt][mt][2], ahf[nxt][mt][3],
                            stg + off);
                    if (MODE != 1)
                        ldsm_x4(alf[nxt][mt][0], alf[nxt][mt][1], alf[nxt][mt][2], alf[nxt][mt][3],
                                stg + TILE_BYTES + off);
                }
                #pragma unroll
                for (int p = 0; p < 4; p++) {
                    int row = wn * 64 + p * 16 + b_r;
                    uint32_t off = swz128(row, (ks + 1) * 2 + b_c);
                    ldsm_x4(bhf[nxt][2*p][0], bhf[nxt][2*p][1], bhf[nxt][2*p+1][0], bhf[nxt][2*p+1][1],
                            stg + 2 * TILE_BYTES + off);
                    if (MODE != 2)
                        ldsm_x4(blf[nxt][2*p][0], blf[nxt][2*p][1], blf[nxt][2*p+1][0], blf[nxt][2*p+1][1],
                                stg + 3 * TILE_BYTES + off);
                }
            }
            #pragma unroll
            for (int mt = 0; mt < 2; mt++)
                #pragma unroll
                for (int nt = 0; nt < 8; nt++) {
                    mma16816(acc[mt][nt], ahf[cur][mt], bhf[cur][nt]);
                    if (MODE != 2)
                        mma16816(acc[mt][nt], ahf[cur][mt], blf[cur][nt]);
                    if (MODE != 1)
                        mma16816(acc[mt][nt], alf[cur][mt], bhf[cur][nt]);
                }
        }

        if (c + 2 < KC)
            load_stage64<MODE>(smb + (uint32_t)((c + 2) % 3) * STAGE_BYTES,
                               Ah, Al, Bh, Bl, K, (c + 2) * 64, tid);
        CP_COMMIT();
    }

    // Epilogue: direct fp32 float2 stores
    #pragma unroll
    for (int mt = 0; mt < 2; mt++) {
        const int row0 = m0 + wm * 32 + mt * 16 + (lane >> 2);
        const int row1 = row0 + 8;
        const float bv0 = bias ? bias[row0] : 0.f;
        const float bv1 = bias ? bias[row1] : 0.f;
        #pragma unroll
        for (int nt = 0; nt < 8; nt++) {
            const int col = n0 + wn * 64 + nt * 8 + (lane & 3) * 2;
            float2 v0 = make_float2(acc[mt][nt][0] * alpha + bv0,
                                    acc[mt][nt][1] * alpha + bv0);
            float2 v1 = make_float2(acc[mt][nt][2] * alpha + bv1,
                                    acc[mt][nt][3] * alpha + bv1);
            *(float2*)(Cp + (size_t)row0 * N + col) = v0;
            *(float2*)(Cp + (size_t)row1 * N + col) = v1;
        }
    }
}

// ============================================================================
// reduce4: out[b][i] = sum_{s<4} part[b*4+s][i]
// ============================================================================
__global__ __launch_bounds__(256)
void reduce4(const float* __restrict__ part, float* __restrict__ out, int n)
{
    const size_t b = blockIdx.z;
    const float4* p0 = (const float4*)(part + (b * 4 + 0) * (size_t)n);
    const float4* p1 = (const float4*)(part + (b * 4 + 1) * (size_t)n);
    const float4* p2 = (const float4*)(part + (b * 4 + 2) * (size_t)n);
    const float4* p3 = (const float4*)(part + (b * 4 + 3) * (size_t)n);
    float4* po = (float4*)(out + b * (size_t)n);
    const int n4 = n >> 2;
    for (int i = blockIdx.x * 256 + threadIdx.x; i < n4; i += gridDim.x * 256) {
        float4 a = p0[i], b1 = p1[i], c = p2[i], d = p3[i];
        po[i] = make_float4(a.x + b1.x + c.x + d.x, a.y + b1.y + c.y + d.y,
                            a.z + b1.z + c.z + d.z, a.w + b1.w + c.w + d.w);
    }
}

// ============================================================================
// split2d: f32 -> fp16 hi/lo (elementwise, z-batched)
// ============================================================================
__global__ __launch_bounds__(256)
void split2d(const float* __restrict__ in, size_t inStride,
             __half* __restrict__ oh, __half* __restrict__ ol,
             size_t oStride, int n)
{
    const size_t b = blockIdx.z;
    const float* p = in + b * inStride;
    __half* ph = oh + b * oStride;
    __half* pl = ol + b * oStride;
    for (int i = blockIdx.x * 256 + threadIdx.x; i < n; i += gridDim.x * 256) {
        float v = p[i];
        __half h = __float2half_rn(v);
        ph[i] = h;
        pl[i] = __float2half_rn(v - __half2float(h));
    }
}

// ============================================================================
// transpose_split: f32 [R][Cl] -> fp16 hi/lo [Cl][R]  (z-batched)
// ============================================================================
__global__ __launch_bounds__(256)
void transpose_split(const float* __restrict__ in, size_t inStride,
                     __half* __restrict__ oh, __half* __restrict__ ol,
                     size_t oStride, int R, int Cl)
{
    __shared__ float t[32][33];
    const size_t b = blockIdx.z;
    const float* p = in + b * inStride;
    __half* ph = oh + b * oStride;
    __half* pl = ol + b * oStride;
    const int r0 = blockIdx.y * 32, c0 = blockIdx.x * 32;
    const int tx = threadIdx.x, ty = threadIdx.y;   // (32, 8)
    #pragma unroll
    for (int i = 0; i < 4; i++)
        t[ty + 8 * i][tx] = p[(size_t)(r0 + ty + 8 * i) * Cl + c0 + tx];
    __syncthreads();
    #pragma unroll
    for (int i = 0; i < 4; i++) {
        float v = t[tx][ty + 8 * i];
        __half h = __float2half_rn(v);
        size_t o = (size_t)(c0 + ty + 8 * i) * R + r0 + tx;
        ph[o] = h;
        pl[o] = __float2half_rn(v - __half2float(h));
    }
}

// ============================================================================
// softmax rows of S (4096 wide) -> attn fp16 (hi only)
// ============================================================================
__global__ __launch_bounds__(256)
void softmax_h(const float* __restrict__ S, __half* __restrict__ ah)
{
    const size_t row = blockIdx.x;
    const float* p = S + row * (size_t)NTOK;
    __half* ph = ah + row * (size_t)NTOK;
    const int tid = threadIdx.x;

    float v[16];
    float mx = -1e30f;
    #pragma unroll
    for (int i = 0; i < 16; i++) {
        v[i] = p[tid + 256 * i];
        mx = fmaxf(mx, v[i]);
    }
    __shared__ float red[256];
    red[tid] = mx;
    __syncthreads();
    #pragma unroll
    for (int s = 128; s > 0; s >>= 1) {
        if (tid < s) red[tid] = fmaxf(red[tid], red[tid + s]);
        __syncthreads();
    }
    mx = red[0];
    __syncthreads();
    float sum = 0.f;
    #pragma unroll
    for (int i = 0; i < 16; i++) { v[i] = __expf(v[i] - mx); sum += v[i]; }
    red[tid] = sum;
    __syncthreads();
    #pragma unroll
    for (int s = 128; s > 0; s >>= 1) {
        if (tid < s) red[tid] += red[tid + s];
        __syncthreads();
    }
    const float inv = 1.0f / red[0];
    #pragma unroll
    for (int i = 0; i < 16; i++)
        ph[tid + 256 * i] = __float2half_rn(v[i] * inv);
}

// ============================================================================
// kernel_launch
// ============================================================================
extern "C" void kernel_launch(void* const* d_in, const int* in_sizes, int n_in,
                              void* d_out, int out_size)
{
    const float* x     = (const float*)d_in[0];
    const float* qkv_w = (const float*)d_in[1];
    const float* qkv_b = (const float*)d_in[2];
    const float* out_w = (const float*)d_in[3];
    const float* out_b = (const float*)d_in[4];
    float* out = (float*)d_out;

    cudaFuncSetAttribute(gemm_f16mp<0>, cudaFuncAttributeMaxDynamicSharedMemorySize, GSMEM);
    cudaFuncSetAttribute(gemm_f16mp<1>, cudaFuncAttributeMaxDynamicSharedMemorySize, GSMEM);
    cudaFuncSetAttribute(gemm_f16mp<2>, cudaFuncAttributeMaxDynamicSharedMemorySize, GSMEM);

    float *qkvp, *Sp, *op;
    __half *xTh, *xTl, *qTh, *qTl, *kTh, *kTl, *oTh, *oTl, *Vh, *Vl, *ath;
    __half *wqh, *wql, *woh, *wol;
    cudaGetSymbolAddress((void**)&qkvp, g_qkv);
    cudaGetSymbolAddress((void**)&Sp,  g_S);
    cudaGetSymbolAddress((void**)&op,  g_o);
    cudaGetSymbolAddress((void**)&xTh, g_xT_h); cudaGetSymbolAddress((void**)&xTl, g_xT_l);
    cudaGetSymbolAddress((void**)&qTh, g_qT_h); cudaGetSymbolAddress((void**)&qTl, g_qT_l);
    cudaGetSymbolAddress((void**)&kTh, g_kT_h); cudaGetSymbolAddress((void**)&kTl, g_kT_l);
    cudaGetSymbolAddress((void**)&oTh, g_oT_h); cudaGetSymbolAddress((void**)&oTl, g_oT_l);
    cudaGetSymbolAddress((void**)&Vh,  g_V_h);  cudaGetSymbolAddress((void**)&Vl,  g_V_l);
    cudaGetSymbolAddress((void**)&ath, g_at_h);
    cudaGetSymbolAddress((void**)&wqh, g_wq_h); cudaGetSymbolAddress((void**)&wql, g_wq_l);
    cudaGetSymbolAddress((void**)&woh, g_wo_h); cudaGetSymbolAddress((void**)&wol, g_wo_l);

    const size_t CN = (size_t)CDIM * NTOK;       // 1M
    const size_t NN = (size_t)NTOK * NTOK;       // 16M

    // --- weights split ---
    split2d<<<dim3(768, 1, 1), 256>>>(qkv_w, 0, wqh, wql, 0, QKV_M * CDIM);
    split2d<<<dim3(256, 1, 1), 256>>>(out_w, 0, woh, wol, 0, CDIM * CDIM);

    // --- xT (transpose+split): [4][256][4096] -> [4][4096][256]
    transpose_split<<<dim3(128, 8, BATCH), dim3(32, 8)>>>(x, CN, xTh, xTl, CN, CDIM, NTOK);

    // --- GEMM1 (3-pass): qkv[b][m=768][tok] = Wq @ x + b
    gemm_f16mp<0><<<dim3(NTOK / 128, QKV_M / 128, BATCH), 256, GSMEM>>>(
        wqh, wql, 0, xTh, xTl, CN, qkvp, (size_t)QKV_M * NTOK,
        QKV_M, NTOK, CDIM, CDIM, 1, 1.0f, qkv_b);

    // --- transpose+split Q and K; split V
    transpose_split<<<dim3(128, 8, BATCH), dim3(32, 8)>>>(qkvp,      (size_t)QKV_M * NTOK, qTh, qTl, CN, CDIM, NTOK);
    transpose_split<<<dim3(128, 8, BATCH), dim3(32, 8)>>>(qkvp + CN, (size_t)QKV_M * NTOK, kTh, kTl, CN, CDIM, NTOK);
    split2d       <<<dim3(2048, 1, BATCH), 256>>>(qkvp + 2 * CN, (size_t)QKV_M * NTOK, Vh, Vl, CN, (int)CN);

    // --- GEMM2 (mode 1: qh.(kh+kl)): S[b][m][n] = (qT . kT) / 16
    gemm_f16mp<1><<<dim3(NTOK / 128, NTOK / 128, BATCH), 256, GSMEM>>>(
        qTh, qTl, CN, kTh, kTl, CN, Sp, NN,
        NTOK, NTOK, CDIM, CDIM, 1, 0.0625f, nullptr);

    // --- softmax rows -> attn hi only
    softmax_h<<<BATCH * NTOK, 256>>>(Sp, ath);

    // --- GEMM3 (mode 2: (Vh+Vl).ah, split-K=4): partials into g_S slabs
    gemm_f16mp<2><<<dim3(NTOK / 128, CDIM / 128, BATCH * 4), 256, GSMEM>>>(
        Vh, Vl, CN, ath, nullptr, NN, Sp, CN,
        CDIM, NTOK, NTOK, NTOK / 4, 4, 1.0f, nullptr);

    // --- reduce split-K partials -> O[b][c][m]
    reduce4<<<dim3(512, 1, BATCH), 256>>>(Sp, op, (int)CN);

    // --- transpose+split O -> oT
    transpose_split<<<dim3(128, 8, BATCH), dim3(32, 8)>>>(op, CN, oTh, oTl, CN, CDIM, NTOK);

    // --- GEMM4 (3-pass): out[b][o][tok] = Wo @ O + b
    gemm_f16mp<0><<<dim3(NTOK / 128, CDIM / 128, BATCH), 256, GSMEM>>>(
        woh, wol, 0, oTh, oTl, CN, out, CN,
        CDIM, NTOK, CDIM, CDIM, 1, 1.0f, out_b);
}